// round 1
// baseline (speedup 1.0000x reference)
#include <cuda_runtime.h>
#include <cuda_bf16.h>
#include <cstdint>

#define B_  2
#define T_  2048
#define NH_ 16
#define HS_ 64
#define C_  (NH_*HS_)   // 1024
#define M_  (B_*T_)     // 4096

// ---------------- scratch (device globals; no allocation allowed) -------------
__device__ float g_xl[(size_t)B_*T_*C_];
__device__ float g_xv[(size_t)B_*T_*C_];
__device__ float g_kraw[(size_t)B_*NH_*T_*HS_];
__device__ float g_k[(size_t)B_*NH_*T_*HS_];
__device__ float g_v[(size_t)B_*NH_*T_*HS_];
__device__ float g_y[(size_t)B_*T_*C_];

// ---------------- SGEMM: 128x128x8, 256 threads, 8x8 per thread ---------------
#define BM 128
#define BN 128
#define BKK 8
#define TM 8
#define TN 8

__global__ void __launch_bounds__(256) sgemm_k(
    const float* __restrict__ A, const float* __restrict__ Bm,
    float* __restrict__ Cm, int M, int N, int K)
{
    __shared__ __align__(16) float As[BKK][BM];
    __shared__ __align__(16) float Bs[BKK][BN];

    const int bx = blockIdx.x;   // N tile
    const int by = blockIdx.y;   // M tile
    const int tid = threadIdx.x;
    const int tx = tid & 15;     // 0..15
    const int ty = tid >> 4;     // 0..15

    const float* Ab = A + (size_t)by * BM * K;
    const float* Bb = Bm + (size_t)bx * BN;

    float acc[TM][TN];
    #pragma unroll
    for (int i = 0; i < TM; i++)
        #pragma unroll
        for (int j = 0; j < TN; j++) acc[i][j] = 0.f;

    const int arow = tid >> 1;          // 0..127
    const int acol = (tid & 1) * 4;     // 0 or 4
    const int brow = tid >> 5;          // 0..7
    const int bcol = (tid & 31) * 4;    // 0..124

    for (int k0 = 0; k0 < K; k0 += BKK) {
        float4 a4 = *(const float4*)(Ab + (size_t)arow * K + k0 + acol);
        As[acol + 0][arow] = a4.x;
        As[acol + 1][arow] = a4.y;
        As[acol + 2][arow] = a4.z;
        As[acol + 3][arow] = a4.w;
        float4 b4 = *(const float4*)(Bb + (size_t)(k0 + brow) * N + bcol);
        *(float4*)(&Bs[brow][bcol]) = b4;
        __syncthreads();

        #pragma unroll
        for (int kk = 0; kk < BKK; kk++) {
            float af[TM], bf[TN];
            #pragma unroll
            for (int i = 0; i < TM; i++) af[i] = As[kk][ty * TM + i];
            #pragma unroll
            for (int j = 0; j < TN; j++) bf[j] = Bs[kk][tx * TN + j];
            #pragma unroll
            for (int i = 0; i < TM; i++)
                #pragma unroll
                for (int j = 0; j < TN; j++)
                    acc[i][j] += af[i] * bf[j];
        }
        __syncthreads();
    }

    #pragma unroll
    for (int i = 0; i < TM; i++) {
        const size_t row = (size_t)by * BM + ty * TM + i;
        #pragma unroll
        for (int j = 0; j < TN; j += 4) {
            float4 o = make_float4(acc[i][j], acc[i][j+1], acc[i][j+2], acc[i][j+3]);
            *(float4*)(Cm + row * N + (size_t)bx * BN + tx * TN + j) = o;
        }
    }
}

// ---------------- EMA scan over time: one thread per (b, h, d) ----------------
__global__ void ema_scan_k(const float* __restrict__ xl,
                           const float* __restrict__ la_coef,
                           float* __restrict__ kraw)
{
    const int idx = blockIdx.x * blockDim.x + threadIdx.x;  // 0..B*C-1
    if (idx >= B_ * C_) return;
    const int b = idx / C_;
    const int c = idx % C_;
    const int h = c / HS_;
    const int d = c % HS_;

    const float alpha = la_coef[h];
    const float onem  = 1.0f - alpha;
    float carry = 0.0f;

    const float* src = xl + (size_t)b * T_ * C_ + c;
    float* dst = kraw + (((size_t)b * NH_ + h) * T_) * HS_ + d;

    for (int t = 0; t < T_; t++) {
        carry = alpha * carry + onem * src[(size_t)t * C_];
        dst[(size_t)t * HS_] = carry;
    }
}

// ---------------- k normalize + kb scale: one warp per row --------------------
__global__ void knorm_k(const float* __restrict__ kraw,
                        const float* __restrict__ kernel_beta,
                        float* __restrict__ kout)
{
    const int row = blockIdx.x * (blockDim.x >> 5) + (threadIdx.x >> 5);
    const int lane = threadIdx.x & 31;
    if (row >= B_ * NH_ * T_) return;
    const int h = (row / T_) % NH_;

    const float2 v = ((const float2*)(kraw + (size_t)row * HS_))[lane];
    float ss = v.x * v.x + v.y * v.y;
    #pragma unroll
    for (int o = 16; o > 0; o >>= 1) ss += __shfl_xor_sync(0xffffffffu, ss, o);

    const float kb = expf(fminf(kernel_beta[h] * 10.0f, 5.0f));
    const float scale = kb * rsqrtf(ss);
    float2 o = make_float2(v.x * scale, v.y * scale);
    ((float2*)(kout + (size_t)row * HS_))[lane] = o;
}

// ---------------- v build (+shift blend) + normalize + vb scale ---------------
__global__ void vmake_k(const float* __restrict__ xv,
                        const float* __restrict__ v_coef,
                        const float* __restrict__ value_beta,
                        float* __restrict__ vout)
{
    const int row = blockIdx.x * (blockDim.x >> 5) + (threadIdx.x >> 5);
    const int lane = threadIdx.x & 31;
    if (row >= B_ * NH_ * T_) return;

    const int t  = row % T_;
    const int bh = row / T_;
    const int h  = bh % NH_;
    const int b  = bh / NH_;

    const float c = v_coef[h];
    const float* cur = xv + (((size_t)b * T_ + t) * C_) + h * HS_;

    const float2 vc = ((const float2*)cur)[lane];
    float2 vn = make_float2(0.f, 0.f);
    if (t + 1 < T_) vn = ((const float2*)(cur + C_))[lane];

    float2 vv = make_float2(vn.x * (1.f - c) + vc.x * c,
                            vn.y * (1.f - c) + vc.y * c);

    float ss = vv.x * vv.x + vv.y * vv.y;
    #pragma unroll
    for (int o = 16; o > 0; o >>= 1) ss += __shfl_xor_sync(0xffffffffu, ss, o);

    const float scale = expf(value_beta[h] * 10.0f) * rsqrtf(ss);
    float2 o = make_float2(vv.x * scale, vv.y * scale);
    ((float2*)(vout + (size_t)row * HS_))[lane] = o;
}

// ---------------- strict-causal flash attention (q == k) ----------------------
// Query at global pos p attends to keys j < p. p=0 outputs zeros.
// One thread per query row; 16-key smem tiles; online softmax.
#define BQ 128
#define TK 16

__global__ void __launch_bounds__(BQ) attn_k(
    const float* __restrict__ Kt, const float* __restrict__ Vt,
    float* __restrict__ Y)
{
    __shared__ __align__(16) float Ks[TK][HS_];
    __shared__ __align__(16) float Vs[TK][HS_];

    const int b = blockIdx.z;
    const int h = blockIdx.y;
    const int p0 = blockIdx.x * BQ;
    const int tid = threadIdx.x;
    const int p = p0 + tid;  // global query position

    const float* Kb = Kt + (((size_t)b * NH_ + h) * T_) * HS_;
    const float* Vb = Vt + (((size_t)b * NH_ + h) * T_) * HS_;

    float q[HS_];
    #pragma unroll
    for (int d4 = 0; d4 < HS_/4; d4++) {
        float4 t4 = ((const float4*)(Kb + (size_t)p * HS_))[d4];
        q[4*d4+0] = t4.x; q[4*d4+1] = t4.y; q[4*d4+2] = t4.z; q[4*d4+3] = t4.w;
    }

    float acc[HS_];
    #pragma unroll
    for (int d = 0; d < HS_; d++) acc[d] = 0.f;
    float m = -1e30f, l = 0.f;

    const int r0 = tid >> 4;       // 0..7
    const int c0 = tid & 15;       // 0..15 (float4 index)
    const int jmax = p0 + BQ - 1;  // strict upper bound on key indices needed

    for (int j0 = 0; j0 < jmax; j0 += TK) {
        // cooperative tile load: 16 rows x 16 float4 = 256 float4 per matrix
        ((float4*)Ks)[tid]       = ((const float4*)(Kb + (size_t)(j0 + r0    ) * HS_))[c0];
        ((float4*)Ks)[tid + BQ]  = ((const float4*)(Kb + (size_t)(j0 + r0 + 8) * HS_))[c0];
        ((float4*)Vs)[tid]       = ((const float4*)(Vb + (size_t)(j0 + r0    ) * HS_))[c0];
        ((float4*)Vs)[tid + BQ]  = ((const float4*)(Vb + (size_t)(j0 + r0 + 8) * HS_))[c0];
        __syncthreads();

        if (p > j0) {  // at least one valid key in this tile
            float s[TK];
            float tm = -1e30f;
            #pragma unroll
            for (int jj = 0; jj < TK; jj++) {
                const int j = j0 + jj;
                const float4* krow = (const float4*)Ks[jj];
                float dot = 0.f;
                #pragma unroll
                for (int d4 = 0; d4 < HS_/4; d4++) {
                    float4 kv = krow[d4];
                    dot += q[4*d4+0] * kv.x;
                    dot += q[4*d4+1] * kv.y;
                    dot += q[4*d4+2] * kv.z;
                    dot += q[4*d4+3] * kv.w;
                }
                s[jj] = (j < p) ? dot : -1e30f;
                tm = fmaxf(tm, s[jj]);
            }
            const float mnew = fmaxf(m, tm);
            const float corr = __expf(m - mnew);
            l *= corr;
            #pragma unroll
            for (int d = 0; d < HS_; d++) acc[d] *= corr;
            #pragma unroll
            for (int jj = 0; jj < TK; jj++) {
                const float pj = __expf(s[jj] - mnew);
                l += pj;
                const float4* vrow = (const float4*)Vs[jj];
                #pragma unroll
                for (int d4 = 0; d4 < HS_/4; d4++) {
                    float4 vv = vrow[d4];
                    acc[4*d4+0] += pj * vv.x;
                    acc[4*d4+1] += pj * vv.y;
                    acc[4*d4+2] += pj * vv.z;
                    acc[4*d4+3] += pj * vv.w;
                }
            }
            m = mnew;
        }
        __syncthreads();
    }

    const float inv_l = (p == 0) ? 0.f : 1.f / l;
    float* yo = Y + (((size_t)b * T_ + p) * C_) + h * HS_;
    #pragma unroll
    for (int d4 = 0; d4 < HS_/4; d4++) {
        float4 o = make_float4(acc[4*d4+0] * inv_l, acc[4*d4+1] * inv_l,
                               acc[4*d4+2] * inv_l, acc[4*d4+3] * inv_l);
        ((float4*)yo)[d4] = o;
    }
}

// ------------------------------- launcher --------------------------------------
extern "C" void kernel_launch(void* const* d_in, const int* in_sizes, int n_in,
                              void* d_out, int out_size)
{
    const float* x           = (const float*)d_in[0];
    const float* W_la        = (const float*)d_in[1];
    const float* la_coef     = (const float*)d_in[2];
    const float* kernel_beta = (const float*)d_in[3];
    const float* value_beta  = (const float*)d_in[4];
    const float* W_v         = (const float*)d_in[5];
    const float* v_coef      = (const float*)d_in[6];
    const float* W_proj      = (const float*)d_in[7];
    float* out = (float*)d_out;

    float *xl, *xv, *kraw, *k, *v, *y;
    cudaGetSymbolAddress((void**)&xl,   g_xl);
    cudaGetSymbolAddress((void**)&xv,   g_xv);
    cudaGetSymbolAddress((void**)&kraw, g_kraw);
    cudaGetSymbolAddress((void**)&k,    g_k);
    cudaGetSymbolAddress((void**)&v,    g_v);
    cudaGetSymbolAddress((void**)&y,    g_y);

    dim3 ggrid(C_/BN, M_/BM);  // (8, 32)

    sgemm_k<<<ggrid, 256>>>(x, W_la, xl, M_, C_, C_);
    sgemm_k<<<ggrid, 256>>>(x, W_v,  xv, M_, C_, C_);

    ema_scan_k<<<(B_*C_)/256, 256>>>(xl, la_coef, kraw);

    knorm_k<<<(B_*NH_*T_)/8, 256>>>(kraw, kernel_beta, k);
    vmake_k<<<(B_*NH_*T_)/8, 256>>>(xv, v_coef, value_beta, v);

    attn_k<<<dim3(T_/BQ, NH_, B_), BQ>>>(k, v, y);

    sgemm_k<<<ggrid, 256>>>(y, W_proj, out, M_, C_, C_);
}

// round 3
// speedup vs baseline: 1.2340x; 1.2340x over previous
#include <cuda_runtime.h>
#include <cuda_bf16.h>
#include <cstdint>

#define B_  2
#define T_  2048
#define NH_ 16
#define HS_ 64
#define C_  (NH_*HS_)   // 1024
#define M_  (B_*T_)     // 4096

// ======================= helpers ==============================================
__device__ __forceinline__ uint32_t smem_u32(const void* p) {
    uint32_t a;
    asm("{ .reg .u64 t; cvta.to.shared.u64 t, %1; cvt.u32.u64 %0, t; }" : "=r"(a) : "l"(p));
    return a;
}
#define CP_ASYNC16(dst_u32, src_ptr) \
    asm volatile("cp.async.cg.shared.global [%0], [%1], 16;" :: "r"(dst_u32), "l"(src_ptr))
#define CP_COMMIT() asm volatile("cp.async.commit_group;" ::: "memory")
#define CP_WAIT(n)  asm volatile("cp.async.wait_group %0;" :: "n"(n) : "memory")

__device__ __forceinline__ void ldm_x4(uint32_t& r0, uint32_t& r1, uint32_t& r2, uint32_t& r3,
                                       uint32_t addr) {
    asm volatile("ldmatrix.sync.aligned.m8n8.x4.shared.b16 {%0,%1,%2,%3}, [%4];"
                 : "=r"(r0), "=r"(r1), "=r"(r2), "=r"(r3) : "r"(addr));
}
__device__ __forceinline__ void ldm_x2(uint32_t& r0, uint32_t& r1, uint32_t addr) {
    asm volatile("ldmatrix.sync.aligned.m8n8.x2.shared.b16 {%0,%1}, [%2];"
                 : "=r"(r0), "=r"(r1) : "r"(addr));
}
__device__ __forceinline__ void mma_bf16(float* c, const uint32_t* a, const uint32_t* b) {
    asm volatile(
        "mma.sync.aligned.m16n8k16.row.col.f32.bf16.bf16.f32 "
        "{%0,%1,%2,%3}, {%4,%5,%6,%7}, {%8,%9}, {%0,%1,%2,%3};"
        : "+f"(c[0]), "+f"(c[1]), "+f"(c[2]), "+f"(c[3])
        : "r"(a[0]), "r"(a[1]), "r"(a[2]), "r"(a[3]), "r"(b[0]), "r"(b[1]));
}

// ---------------- scratch (device globals; no allocation allowed) -------------
__device__ float g_xl[(size_t)B_*T_*C_];
__device__ float g_xv[(size_t)B_*T_*C_];
__device__ float g_kraw[(size_t)B_*NH_*T_*HS_];
__device__ float g_k[(size_t)B_*NH_*T_*HS_];
__device__ float g_v[(size_t)B_*NH_*T_*HS_];
__device__ float g_y[(size_t)B_*T_*C_];

__device__ __nv_bfloat16 g_Ah[(size_t)M_*C_];
__device__ __nv_bfloat16 g_Al[(size_t)M_*C_];
__device__ __nv_bfloat16 g_Wla_h[(size_t)C_*C_];
__device__ __nv_bfloat16 g_Wla_l[(size_t)C_*C_];
__device__ __nv_bfloat16 g_Wv_h[(size_t)C_*C_];
__device__ __nv_bfloat16 g_Wv_l[(size_t)C_*C_];
__device__ __nv_bfloat16 g_Wp_h[(size_t)C_*C_];
__device__ __nv_bfloat16 g_Wp_l[(size_t)C_*C_];

// ================= fp32 -> bf16 hi/lo split (no transpose) ====================
__global__ void __launch_bounds__(256) split_bf16_k(
    const float* __restrict__ X, __nv_bfloat16* __restrict__ H,
    __nv_bfloat16* __restrict__ L, int n4)
{
    int i = blockIdx.x * blockDim.x + threadIdx.x;
    if (i >= n4) return;
    float4 v = ((const float4*)X)[i];
    __nv_bfloat16 h0 = __float2bfloat16_rn(v.x);
    __nv_bfloat16 h1 = __float2bfloat16_rn(v.y);
    __nv_bfloat16 h2 = __float2bfloat16_rn(v.z);
    __nv_bfloat16 h3 = __float2bfloat16_rn(v.w);
    __nv_bfloat16 l0 = __float2bfloat16_rn(v.x - __bfloat162float(h0));
    __nv_bfloat16 l1 = __float2bfloat16_rn(v.y - __bfloat162float(h1));
    __nv_bfloat16 l2 = __float2bfloat16_rn(v.z - __bfloat162float(h2));
    __nv_bfloat16 l3 = __float2bfloat16_rn(v.w - __bfloat162float(h3));
    __nv_bfloat162* Hp = (__nv_bfloat162*)H;
    __nv_bfloat162* Lp = (__nv_bfloat162*)L;
    Hp[2*i]   = __nv_bfloat162(h0, h1);
    Hp[2*i+1] = __nv_bfloat162(h2, h3);
    Lp[2*i]   = __nv_bfloat162(l0, l1);
    Lp[2*i+1] = __nv_bfloat162(l2, l3);
}

// ========== fp32 [K,N] -> bf16 hi/lo transposed to [N,K] (K-major) ============
__global__ void tsplit_bf16_k(const float* __restrict__ W,
                              __nv_bfloat16* __restrict__ TH,
                              __nv_bfloat16* __restrict__ TL)
{
    __shared__ float tile[32][33];
    const int n0 = blockIdx.x * 32, k0 = blockIdx.y * 32;
    const int tx = threadIdx.x, ty = threadIdx.y;  // 32 x 8
    #pragma unroll
    for (int j = ty; j < 32; j += 8)
        tile[j][tx] = W[(size_t)(k0 + j) * C_ + n0 + tx];
    __syncthreads();
    #pragma unroll
    for (int j = ty; j < 32; j += 8) {
        float v = tile[tx][j];  // = W[k0+tx][n0+j]
        __nv_bfloat16 h = __float2bfloat16_rn(v);
        __nv_bfloat16 l = __float2bfloat16_rn(v - __bfloat162float(h));
        TH[(size_t)(n0 + j) * C_ + k0 + tx] = h;
        TL[(size_t)(n0 + j) * C_ + k0 + tx] = l;
    }
}

// ============ HMMA bf16 split GEMM: C[M,N] = A[M,K] @ B^T[N,K] ================
// A hi/lo bf16 [M,K] row-major; B hi/lo bf16 [N,K] row-major (W pre-transposed).
// 3 accumulation passes: Ah*Bh + Ah*Bl + Al*Bh into fp32 register accumulators.
#define GBM 128
#define GBN 128
#define GBK 32
#define GK  1024
#define GNN 1024
#define LDS_H (GBK + 8)          // halves per smem row (pad for bank spread)
#define NITER ((GK / GBK) * 3)   // 96

__global__ void __launch_bounds__(256) gemm_tc_k(
    const __nv_bfloat16* __restrict__ Ah, const __nv_bfloat16* __restrict__ Al,
    const __nv_bfloat16* __restrict__ Bh, const __nv_bfloat16* __restrict__ Bl,
    float* __restrict__ Cg)
{
    __shared__ __align__(16) __nv_bfloat16 As[2][GBM][LDS_H];
    __shared__ __align__(16) __nv_bfloat16 Bs[2][GBN][LDS_H];

    const int n0 = blockIdx.x * GBN;
    const int m0 = blockIdx.y * GBM;
    const int tid  = threadIdx.x;
    const int wid  = tid >> 5;
    const int lane = tid & 31;
    const int wm = (wid >> 2) * 64;   // warp m offset (0 or 64)
    const int wn = (wid & 3) * 32;    // warp n offset (0..96)

    const __nv_bfloat16* Aps[3] = {Ah, Ah, Al};
    const __nv_bfloat16* Bps[3] = {Bh, Bl, Bh};

    // per-thread global-load mapping: 2 x 16B per matrix per iter
    const int r0  = tid >> 2;        // 0..63
    const int c16 = (tid & 3) * 8;   // half-offset of 16B segment

    float acc[4][4][4];
    #pragma unroll
    for (int i = 0; i < 4; i++)
        #pragma unroll
        for (int j = 0; j < 4; j++)
            #pragma unroll
            for (int e = 0; e < 4; e++) acc[i][j][e] = 0.f;

    auto load_tile = [&](int stage, int it) {
        const int pass = it >> 5;
        const int k0 = (it & 31) * GBK;
        const __nv_bfloat16* Ap = Aps[pass];
        const __nv_bfloat16* Bp = Bps[pass];
        #pragma unroll
        for (int r = 0; r < 2; r++) {
            const int row = r0 + r * 64;
            CP_ASYNC16(smem_u32(&As[stage][row][c16]),
                       Ap + (size_t)(m0 + row) * GK + k0 + c16);
            CP_ASYNC16(smem_u32(&Bs[stage][row][c16]),
                       Bp + (size_t)(n0 + row) * GK + k0 + c16);
        }
    };

    load_tile(0, 0);
    CP_COMMIT();

    #pragma unroll 1
    for (int it = 0; it < NITER; it++) {
        const int stage = it & 1;
        if (it + 1 < NITER) {
            load_tile(stage ^ 1, it + 1);
            CP_COMMIT();
            CP_WAIT(1);
        } else {
            CP_WAIT(0);
        }
        __syncthreads();

        #pragma unroll
        for (int ks = 0; ks < 2; ks++) {
            const int koff = ks * 16;
            uint32_t afr[4][4], bfr[4][2];
            #pragma unroll
            for (int mi = 0; mi < 4; mi++) {
                uint32_t addr = smem_u32(&As[stage][wm + mi*16 + (lane & 15)]
                                            [koff + ((lane >> 4) & 1) * 8]);
                ldm_x4(afr[mi][0], afr[mi][1], afr[mi][2], afr[mi][3], addr);
            }
            #pragma unroll
            for (int ni = 0; ni < 4; ni++) {
                uint32_t addr = smem_u32(&Bs[stage][wn + ni*8 + (lane & 7)]
                                            [koff + ((lane >> 3) & 1) * 8]);
                ldm_x2(bfr[ni][0], bfr[ni][1], addr);
            }
            #pragma unroll
            for (int mi = 0; mi < 4; mi++)
                #pragma unroll
                for (int ni = 0; ni < 4; ni++)
                    mma_bf16(acc[mi][ni], afr[mi], bfr[ni]);
        }
        __syncthreads();
    }

    // epilogue: acc (mi,ni) -> rows m0+wm+mi*16+{g, g+8}, cols n0+wn+ni*8+(t*2,+1)
    const int g = lane >> 2, t = lane & 3;
    #pragma unroll
    for (int mi = 0; mi < 4; mi++) {
        float* row0 = Cg + (size_t)(m0 + wm + mi*16 + g)     * GNN + n0 + wn;
        float* row1 = Cg + (size_t)(m0 + wm + mi*16 + g + 8) * GNN + n0 + wn;
        #pragma unroll
        for (int ni = 0; ni < 4; ni++) {
            *(float2*)(row0 + ni*8 + t*2) = make_float2(acc[mi][ni][0], acc[mi][ni][1]);
            *(float2*)(row1 + ni*8 + t*2) = make_float2(acc[mi][ni][2], acc[mi][ni][3]);
        }
    }
}

// ---------------- EMA scan over time: one thread per (b, h, d) ----------------
__global__ void ema_scan_k(const float* __restrict__ xl,
                           const float* __restrict__ la_coef,
                           float* __restrict__ kraw)
{
    const int idx = blockIdx.x * blockDim.x + threadIdx.x;
    if (idx >= B_ * C_) return;
    const int b = idx / C_;
    const int c = idx % C_;
    const int h = c / HS_;
    const int d = c % HS_;

    const float alpha = la_coef[h];
    const float onem  = 1.0f - alpha;
    float carry = 0.0f;

    const float* src = xl + (size_t)b * T_ * C_ + c;
    float* dst = kraw + (((size_t)b * NH_ + h) * T_) * HS_ + d;

    for (int t = 0; t < T_; t++) {
        carry = alpha * carry + onem * src[(size_t)t * C_];
        dst[(size_t)t * HS_] = carry;
    }
}

// ---------------- k normalize + kb scale: one warp per row --------------------
__global__ void knorm_k(const float* __restrict__ kraw,
                        const float* __restrict__ kernel_beta,
                        float* __restrict__ kout)
{
    const int row = blockIdx.x * (blockDim.x >> 5) + (threadIdx.x >> 5);
    const int lane = threadIdx.x & 31;
    if (row >= B_ * NH_ * T_) return;
    const int h = (row / T_) % NH_;

    const float2 v = ((const float2*)(kraw + (size_t)row * HS_))[lane];
    float ss = v.x * v.x + v.y * v.y;
    #pragma unroll
    for (int o = 16; o > 0; o >>= 1) ss += __shfl_xor_sync(0xffffffffu, ss, o);

    const float kb = expf(fminf(kernel_beta[h] * 10.0f, 5.0f));
    const float scale = kb * rsqrtf(ss);
    float2 o = make_float2(v.x * scale, v.y * scale);
    ((float2*)(kout + (size_t)row * HS_))[lane] = o;
}

// ---------------- v build (+shift blend) + normalize + vb scale ---------------
__global__ void vmake_k(const float* __restrict__ xv,
                        const float* __restrict__ v_coef,
                        const float* __restrict__ value_beta,
                        float* __restrict__ vout)
{
    const int row = blockIdx.x * (blockDim.x >> 5) + (threadIdx.x >> 5);
    const int lane = threadIdx.x & 31;
    if (row >= B_ * NH_ * T_) return;

    const int t  = row % T_;
    const int bh = row / T_;
    const int h  = bh % NH_;
    const int b  = bh / NH_;

    const float c = v_coef[h];
    const float* cur = xv + (((size_t)b * T_ + t) * C_) + h * HS_;

    const float2 vc = ((const float2*)cur)[lane];
    float2 vn = make_float2(0.f, 0.f);
    if (t + 1 < T_) vn = ((const float2*)(cur + C_))[lane];

    float2 vv = make_float2(vn.x * (1.f - c) + vc.x * c,
                            vn.y * (1.f - c) + vc.y * c);

    float ss = vv.x * vv.x + vv.y * vv.y;
    #pragma unroll
    for (int o = 16; o > 0; o >>= 1) ss += __shfl_xor_sync(0xffffffffu, ss, o);

    const float scale = expf(value_beta[h] * 10.0f) * rsqrtf(ss);
    float2 o = make_float2(vv.x * scale, vv.y * scale);
    ((float2*)(vout + (size_t)row * HS_))[lane] = o;
}

// ---------------- strict-causal flash attention (q == k) ----------------------
#define BQ 128
#define TK 16

__global__ void __launch_bounds__(BQ) attn_k(
    const float* __restrict__ Kt, const float* __restrict__ Vt,
    float* __restrict__ Y)
{
    __shared__ __align__(16) float Ks[TK][HS_];
    __shared__ __align__(16) float Vs[TK][HS_];

    const int b = blockIdx.z;
    const int h = blockIdx.y;
    const int p0 = blockIdx.x * BQ;
    const int tid = threadIdx.x;
    const int p = p0 + tid;

    const float* Kb = Kt + (((size_t)b * NH_ + h) * T_) * HS_;
    const float* Vb = Vt + (((size_t)b * NH_ + h) * T_) * HS_;

    float q[HS_];
    #pragma unroll
    for (int d4 = 0; d4 < HS_/4; d4++) {
        float4 t4 = ((const float4*)(Kb + (size_t)p * HS_))[d4];
        q[4*d4+0] = t4.x; q[4*d4+1] = t4.y; q[4*d4+2] = t4.z; q[4*d4+3] = t4.w;
    }

    float acc[HS_];
    #pragma unroll
    for (int d = 0; d < HS_; d++) acc[d] = 0.f;
    float m = -1e30f, l = 0.f;

    const int r0 = tid >> 4;
    const int c0 = tid & 15;
    const int jmax = p0 + BQ - 1;

    for (int j0 = 0; j0 < jmax; j0 += TK) {
        ((float4*)Ks)[tid]       = ((const float4*)(Kb + (size_t)(j0 + r0    ) * HS_))[c0];
        ((float4*)Ks)[tid + BQ]  = ((const float4*)(Kb + (size_t)(j0 + r0 + 8) * HS_))[c0];
        ((float4*)Vs)[tid]       = ((const float4*)(Vb + (size_t)(j0 + r0    ) * HS_))[c0];
        ((float4*)Vs)[tid + BQ]  = ((const float4*)(Vb + (size_t)(j0 + r0 + 8) * HS_))[c0];
        __syncthreads();

        if (p > j0) {
            float s[TK];
            float tm = -1e30f;
            #pragma unroll
            for (int jj = 0; jj < TK; jj++) {
                const int j = j0 + jj;
                const float4* krow = (const float4*)Ks[jj];
                float dot = 0.f;
                #pragma unroll
                for (int d4 = 0; d4 < HS_/4; d4++) {
                    float4 kv = krow[d4];
                    dot += q[4*d4+0] * kv.x;
                    dot += q[4*d4+1] * kv.y;
                    dot += q[4*d4+2] * kv.z;
                    dot += q[4*d4+3] * kv.w;
                }
                s[jj] = (j < p) ? dot : -1e30f;
                tm = fmaxf(tm, s[jj]);
            }
            const float mnew = fmaxf(m, tm);
            const float corr = __expf(m - mnew);
            l *= corr;
            #pragma unroll
            for (int d = 0; d < HS_; d++) acc[d] *= corr;
            #pragma unroll
            for (int jj = 0; jj < TK; jj++) {
                const float pj = __expf(s[jj] - mnew);
                l += pj;
                const float4* vrow = (const float4*)Vs[jj];
                #pragma unroll
                for (int d4 = 0; d4 < HS_/4; d4++) {
                    float4 vv = vrow[d4];
                    acc[4*d4+0] += pj * vv.x;
                    acc[4*d4+1] += pj * vv.y;
                    acc[4*d4+2] += pj * vv.z;
                    acc[4*d4+3] += pj * vv.w;
                }
            }
            m = mnew;
        }
        __syncthreads();
    }

    const float inv_l = (p == 0) ? 0.f : 1.f / l;
    float* yo = Y + (((size_t)b * T_ + p) * C_) + h * HS_;
    #pragma unroll
    for (int d4 = 0; d4 < HS_/4; d4++) {
        float4 o = make_float4(acc[4*d4+0] * inv_l, acc[4*d4+1] * inv_l,
                               acc[4*d4+2] * inv_l, acc[4*d4+3] * inv_l);
        ((float4*)yo)[d4] = o;
    }
}

// ------------------------------- launcher --------------------------------------
extern "C" void kernel_launch(void* const* d_in, const int* in_sizes, int n_in,
                              void* d_out, int out_size)
{
    const float* x           = (const float*)d_in[0];
    const float* W_la        = (const float*)d_in[1];
    const float* la_coef     = (const float*)d_in[2];
    const float* kernel_beta = (const float*)d_in[3];
    const float* value_beta  = (const float*)d_in[4];
    const float* W_v         = (const float*)d_in[5];
    const float* v_coef      = (const float*)d_in[6];
    const float* W_proj      = (const float*)d_in[7];
    float* out = (float*)d_out;

    float *xl, *xv, *kraw, *k, *v, *y;
    __nv_bfloat16 *Ah, *Al, *Wla_h, *Wla_l, *Wv_h, *Wv_l, *Wp_h, *Wp_l;
    cudaGetSymbolAddress((void**)&xl,   g_xl);
    cudaGetSymbolAddress((void**)&xv,   g_xv);
    cudaGetSymbolAddress((void**)&kraw, g_kraw);
    cudaGetSymbolAddress((void**)&k,    g_k);
    cudaGetSymbolAddress((void**)&v,    g_v);
    cudaGetSymbolAddress((void**)&y,    g_y);
    cudaGetSymbolAddress((void**)&Ah,   g_Ah);
    cudaGetSymbolAddress((void**)&Al,   g_Al);
    cudaGetSymbolAddress((void**)&Wla_h, g_Wla_h);
    cudaGetSymbolAddress((void**)&Wla_l, g_Wla_l);
    cudaGetSymbolAddress((void**)&Wv_h,  g_Wv_h);
    cudaGetSymbolAddress((void**)&Wv_l,  g_Wv_l);
    cudaGetSymbolAddress((void**)&Wp_h,  g_Wp_h);
    cudaGetSymbolAddress((void**)&Wp_l,  g_Wp_l);

    const dim3 ggrid(C_ / GBN, M_ / GBM);   // (8, 32)
    const dim3 tgrid(32, 32), tblk(32, 8);
    const int n4 = (M_ * C_) / 4;

    split_bf16_k<<<(n4 + 255) / 256, 256>>>(x, Ah, Al, n4);
    tsplit_bf16_k<<<tgrid, tblk>>>(W_la,   Wla_h, Wla_l);
    tsplit_bf16_k<<<tgrid, tblk>>>(W_v,    Wv_h,  Wv_l);
    tsplit_bf16_k<<<tgrid, tblk>>>(W_proj, Wp_h,  Wp_l);

    gemm_tc_k<<<ggrid, 256>>>(Ah, Al, Wla_h, Wla_l, xl);
    gemm_tc_k<<<ggrid, 256>>>(Ah, Al, Wv_h,  Wv_l,  xv);

    ema_scan_k<<<(B_*C_)/256, 256>>>(xl, la_coef, kraw);

    knorm_k<<<(B_*NH_*T_)/8, 256>>>(kraw, kernel_beta, k);
    vmake_k<<<(B_*NH_*T_)/8, 256>>>(xv, v_coef, value_beta, v);

    attn_k<<<dim3(T_/BQ, NH_, B_), BQ>>>(k, v, y);

    split_bf16_k<<<(n4 + 255) / 256, 256>>>(y, Ah, Al, n4);
    gemm_tc_k<<<ggrid, 256>>>(Ah, Al, Wp_h, Wp_l, out);
}

// round 4
// speedup vs baseline: 3.0239x; 2.4504x over previous
#include <cuda_runtime.h>
#include <cuda_bf16.h>
#include <cstdint>

#define B_  2
#define T_  2048
#define NH_ 16
#define HS_ 64
#define C_  (NH_*HS_)   // 1024
#define M_  (B_*T_)     // 4096

// ======================= helpers ==============================================
__device__ __forceinline__ uint32_t smem_u32(const void* p) {
    uint32_t a;
    asm("{ .reg .u64 t; cvta.to.shared.u64 t, %1; cvt.u32.u64 %0, t; }" : "=r"(a) : "l"(p));
    return a;
}
#define CP_ASYNC16(dst_u32, src_ptr) \
    asm volatile("cp.async.cg.shared.global [%0], [%1], 16;" :: "r"(dst_u32), "l"(src_ptr))
#define CP_COMMIT() asm volatile("cp.async.commit_group;" ::: "memory")
#define CP_WAIT(n)  asm volatile("cp.async.wait_group %0;" :: "n"(n) : "memory")

__device__ __forceinline__ void ldm_x4(uint32_t& r0, uint32_t& r1, uint32_t& r2, uint32_t& r3,
                                       uint32_t addr) {
    asm volatile("ldmatrix.sync.aligned.m8n8.x4.shared.b16 {%0,%1,%2,%3}, [%4];"
                 : "=r"(r0), "=r"(r1), "=r"(r2), "=r"(r3) : "r"(addr));
}
__device__ __forceinline__ void ldm_x2(uint32_t& r0, uint32_t& r1, uint32_t addr) {
    asm volatile("ldmatrix.sync.aligned.m8n8.x2.shared.b16 {%0,%1}, [%2];"
                 : "=r"(r0), "=r"(r1) : "r"(addr));
}
__device__ __forceinline__ void mma_bf16(float* c, const uint32_t* a, const uint32_t* b) {
    asm volatile(
        "mma.sync.aligned.m16n8k16.row.col.f32.bf16.bf16.f32 "
        "{%0,%1,%2,%3}, {%4,%5,%6,%7}, {%8,%9}, {%0,%1,%2,%3};"
        : "+f"(c[0]), "+f"(c[1]), "+f"(c[2]), "+f"(c[3])
        : "r"(a[0]), "r"(a[1]), "r"(a[2]), "r"(a[3]), "r"(b[0]), "r"(b[1]));
}
__device__ __forceinline__ uint32_t pack_bf16(float a, float b) {
    __nv_bfloat162 h(__float2bfloat16_rn(a), __float2bfloat16_rn(b));
    return *(uint32_t*)&h;
}

// ---------------- scratch (device globals; no allocation allowed) -------------
__device__ float g_xl[(size_t)B_*T_*C_];
__device__ float g_xv[(size_t)B_*T_*C_];
__device__ float g_kraw[(size_t)B_*NH_*T_*HS_];
__device__ float g_v[(size_t)B_*NH_*T_*HS_];

__device__ __nv_bfloat16 g_Ah[(size_t)M_*C_];
__device__ __nv_bfloat16 g_Al[(size_t)M_*C_];
__device__ __nv_bfloat16 g_Wla_h[(size_t)C_*C_];
__device__ __nv_bfloat16 g_Wla_l[(size_t)C_*C_];
__device__ __nv_bfloat16 g_Wv_h[(size_t)C_*C_];
__device__ __nv_bfloat16 g_Wv_l[(size_t)C_*C_];
__device__ __nv_bfloat16 g_Wp_h[(size_t)C_*C_];
__device__ __nv_bfloat16 g_Wp_l[(size_t)C_*C_];
__device__ __nv_bfloat16 g_kh[(size_t)B_*NH_*T_*HS_];
__device__ __nv_bfloat16 g_kl[(size_t)B_*NH_*T_*HS_];
__device__ __nv_bfloat16 g_vth[(size_t)B_*NH_*HS_*T_];   // [b,h,d,t]
__device__ __nv_bfloat16 g_vtl[(size_t)B_*NH_*HS_*T_];

// ================= fp32 -> bf16 hi/lo split (no transpose) ====================
__global__ void __launch_bounds__(256) split_bf16_k(
    const float* __restrict__ X, __nv_bfloat16* __restrict__ H,
    __nv_bfloat16* __restrict__ L, int n4)
{
    int i = blockIdx.x * blockDim.x + threadIdx.x;
    if (i >= n4) return;
    float4 v = ((const float4*)X)[i];
    __nv_bfloat16 h0 = __float2bfloat16_rn(v.x);
    __nv_bfloat16 h1 = __float2bfloat16_rn(v.y);
    __nv_bfloat16 h2 = __float2bfloat16_rn(v.z);
    __nv_bfloat16 h3 = __float2bfloat16_rn(v.w);
    __nv_bfloat16 l0 = __float2bfloat16_rn(v.x - __bfloat162float(h0));
    __nv_bfloat16 l1 = __float2bfloat16_rn(v.y - __bfloat162float(h1));
    __nv_bfloat16 l2 = __float2bfloat16_rn(v.z - __bfloat162float(h2));
    __nv_bfloat16 l3 = __float2bfloat16_rn(v.w - __bfloat162float(h3));
    __nv_bfloat162* Hp = (__nv_bfloat162*)H;
    __nv_bfloat162* Lp = (__nv_bfloat162*)L;
    Hp[2*i]   = __nv_bfloat162(h0, h1);
    Hp[2*i+1] = __nv_bfloat162(h2, h3);
    Lp[2*i]   = __nv_bfloat162(l0, l1);
    Lp[2*i+1] = __nv_bfloat162(l2, l3);
}

// ========== fp32 [K,N] -> bf16 hi/lo transposed to [N,K] (K-major) ============
__global__ void tsplit_bf16_k(const float* __restrict__ W,
                              __nv_bfloat16* __restrict__ TH,
                              __nv_bfloat16* __restrict__ TL)
{
    __shared__ float tile[32][33];
    const int n0 = blockIdx.x * 32, k0 = blockIdx.y * 32;
    const int tx = threadIdx.x, ty = threadIdx.y;  // 32 x 8
    #pragma unroll
    for (int j = ty; j < 32; j += 8)
        tile[j][tx] = W[(size_t)(k0 + j) * C_ + n0 + tx];
    __syncthreads();
    #pragma unroll
    for (int j = ty; j < 32; j += 8) {
        float v = tile[tx][j];
        __nv_bfloat16 h = __float2bfloat16_rn(v);
        __nv_bfloat16 l = __float2bfloat16_rn(v - __bfloat162float(h));
        TH[(size_t)(n0 + j) * C_ + k0 + tx] = h;
        TL[(size_t)(n0 + j) * C_ + k0 + tx] = l;
    }
}

// ============ HMMA bf16 split GEMM: C[M,N] = A[M,K] @ B^T[N,K] ================
#define GBM 128
#define GBN 128
#define GBK 32
#define GK  1024
#define GNN 1024
#define LDS_H (GBK + 8)
#define NITER ((GK / GBK) * 3)

__global__ void __launch_bounds__(256) gemm_tc_k(
    const __nv_bfloat16* __restrict__ Ah, const __nv_bfloat16* __restrict__ Al,
    const __nv_bfloat16* __restrict__ Bh, const __nv_bfloat16* __restrict__ Bl,
    float* __restrict__ Cg)
{
    __shared__ __align__(16) __nv_bfloat16 As[2][GBM][LDS_H];
    __shared__ __align__(16) __nv_bfloat16 Bs[2][GBN][LDS_H];

    const int n0 = blockIdx.x * GBN;
    const int m0 = blockIdx.y * GBM;
    const int tid  = threadIdx.x;
    const int wid  = tid >> 5;
    const int lane = tid & 31;
    const int wm = (wid >> 2) * 64;
    const int wn = (wid & 3) * 32;

    const __nv_bfloat16* Aps[3] = {Ah, Ah, Al};
    const __nv_bfloat16* Bps[3] = {Bh, Bl, Bh};

    const int r0  = tid >> 2;
    const int c16 = (tid & 3) * 8;

    float acc[4][4][4];
    #pragma unroll
    for (int i = 0; i < 4; i++)
        #pragma unroll
        for (int j = 0; j < 4; j++)
            #pragma unroll
            for (int e = 0; e < 4; e++) acc[i][j][e] = 0.f;

    auto load_tile = [&](int stage, int it) {
        const int pass = it >> 5;
        const int k0 = (it & 31) * GBK;
        const __nv_bfloat16* Ap = Aps[pass];
        const __nv_bfloat16* Bp = Bps[pass];
        #pragma unroll
        for (int r = 0; r < 2; r++) {
            const int row = r0 + r * 64;
            CP_ASYNC16(smem_u32(&As[stage][row][c16]),
                       Ap + (size_t)(m0 + row) * GK + k0 + c16);
            CP_ASYNC16(smem_u32(&Bs[stage][row][c16]),
                       Bp + (size_t)(n0 + row) * GK + k0 + c16);
        }
    };

    load_tile(0, 0);
    CP_COMMIT();

    #pragma unroll 1
    for (int it = 0; it < NITER; it++) {
        const int stage = it & 1;
        if (it + 1 < NITER) {
            load_tile(stage ^ 1, it + 1);
            CP_COMMIT();
            CP_WAIT(1);
        } else {
            CP_WAIT(0);
        }
        __syncthreads();

        #pragma unroll
        for (int ks = 0; ks < 2; ks++) {
            const int koff = ks * 16;
            uint32_t afr[4][4], bfr[4][2];
            #pragma unroll
            for (int mi = 0; mi < 4; mi++) {
                uint32_t addr = smem_u32(&As[stage][wm + mi*16 + (lane & 15)]
                                            [koff + ((lane >> 4) & 1) * 8]);
                ldm_x4(afr[mi][0], afr[mi][1], afr[mi][2], afr[mi][3], addr);
            }
            #pragma unroll
            for (int ni = 0; ni < 4; ni++) {
                uint32_t addr = smem_u32(&Bs[stage][wn + ni*8 + (lane & 7)]
                                            [koff + ((lane >> 3) & 1) * 8]);
                ldm_x2(bfr[ni][0], bfr[ni][1], addr);
            }
            #pragma unroll
            for (int mi = 0; mi < 4; mi++)
                #pragma unroll
                for (int ni = 0; ni < 4; ni++)
                    mma_bf16(acc[mi][ni], afr[mi], bfr[ni]);
        }
        __syncthreads();
    }

    const int g = lane >> 2, t = lane & 3;
    #pragma unroll
    for (int mi = 0; mi < 4; mi++) {
        float* row0 = Cg + (size_t)(m0 + wm + mi*16 + g)     * GNN + n0 + wn;
        float* row1 = Cg + (size_t)(m0 + wm + mi*16 + g + 8) * GNN + n0 + wn;
        #pragma unroll
        for (int ni = 0; ni < 4; ni++) {
            *(float2*)(row0 + ni*8 + t*2) = make_float2(acc[mi][ni][0], acc[mi][ni][1]);
            *(float2*)(row1 + ni*8 + t*2) = make_float2(acc[mi][ni][2], acc[mi][ni][3]);
        }
    }
}

// ---------------- EMA scan over time: one thread per (b, h, d) ----------------
__global__ void ema_scan_k(const float* __restrict__ xl,
                           const float* __restrict__ la_coef,
                           float* __restrict__ kraw)
{
    const int idx = blockIdx.x * blockDim.x + threadIdx.x;
    if (idx >= B_ * C_) return;
    const int b = idx / C_;
    const int c = idx % C_;
    const int h = c / HS_;
    const int d = c % HS_;

    const float alpha = la_coef[h];
    const float onem  = 1.0f - alpha;
    float carry = 0.0f;

    const float* src = xl + (size_t)b * T_ * C_ + c;
    float* dst = kraw + (((size_t)b * NH_ + h) * T_) * HS_ + d;

    for (int t = 0; t < T_; t++) {
        carry = alpha * carry + onem * src[(size_t)t * C_];
        dst[(size_t)t * HS_] = carry;
    }
}

// ------- k normalize + kb scale -> bf16 hi/lo, one warp per row ---------------
__global__ void knorm_bf16_k(const float* __restrict__ kraw,
                             const float* __restrict__ kernel_beta,
                             __nv_bfloat16* __restrict__ kh,
                             __nv_bfloat16* __restrict__ kl)
{
    const int row = blockIdx.x * (blockDim.x >> 5) + (threadIdx.x >> 5);
    const int lane = threadIdx.x & 31;
    if (row >= B_ * NH_ * T_) return;
    const int h = (row / T_) % NH_;

    const float2 v = ((const float2*)(kraw + (size_t)row * HS_))[lane];
    float ss = v.x * v.x + v.y * v.y;
    #pragma unroll
    for (int o = 16; o > 0; o >>= 1) ss += __shfl_xor_sync(0xffffffffu, ss, o);

    const float kb = expf(fminf(kernel_beta[h] * 10.0f, 5.0f));
    const float scale = kb * rsqrtf(ss);
    float o0 = v.x * scale, o1 = v.y * scale;
    __nv_bfloat16 h0 = __float2bfloat16_rn(o0), h1 = __float2bfloat16_rn(o1);
    __nv_bfloat16 l0 = __float2bfloat16_rn(o0 - __bfloat162float(h0));
    __nv_bfloat16 l1 = __float2bfloat16_rn(o1 - __bfloat162float(h1));
    ((__nv_bfloat162*)(kh + (size_t)row * HS_))[lane] = __nv_bfloat162(h0, h1);
    ((__nv_bfloat162*)(kl + (size_t)row * HS_))[lane] = __nv_bfloat162(l0, l1);
}

// ---------------- v build (+shift blend) + normalize + vb scale (fp32) --------
__global__ void vmake_k(const float* __restrict__ xv,
                        const float* __restrict__ v_coef,
                        const float* __restrict__ value_beta,
                        float* __restrict__ vout)
{
    const int row = blockIdx.x * (blockDim.x >> 5) + (threadIdx.x >> 5);
    const int lane = threadIdx.x & 31;
    if (row >= B_ * NH_ * T_) return;

    const int t  = row % T_;
    const int bh = row / T_;
    const int h  = bh % NH_;
    const int b  = bh / NH_;

    const float c = v_coef[h];
    const float* cur = xv + (((size_t)b * T_ + t) * C_) + h * HS_;

    const float2 vc = ((const float2*)cur)[lane];
    float2 vn = make_float2(0.f, 0.f);
    if (t + 1 < T_) vn = ((const float2*)(cur + C_))[lane];

    float2 vv = make_float2(vn.x * (1.f - c) + vc.x * c,
                            vn.y * (1.f - c) + vc.y * c);

    float ss = vv.x * vv.x + vv.y * vv.y;
    #pragma unroll
    for (int o = 16; o > 0; o >>= 1) ss += __shfl_xor_sync(0xffffffffu, ss, o);

    const float scale = expf(value_beta[h] * 10.0f) * rsqrtf(ss);
    float2 o = make_float2(vv.x * scale, vv.y * scale);
    ((float2*)(vout + (size_t)row * HS_))[lane] = o;
}

// ------ v [b,h,t,d] fp32 -> transposed bf16 hi/lo [b,h,d,t] -------------------
__global__ void vtsplit_k(const float* __restrict__ v,
                          __nv_bfloat16* __restrict__ vth,
                          __nv_bfloat16* __restrict__ vtl)
{
    __shared__ float tl[64][65];
    const int t0 = blockIdx.x * 64;
    const int bh = blockIdx.y;
    const int tid = threadIdx.x;
    const float* src = v + (size_t)bh * T_ * HS_ + (size_t)t0 * HS_;
    #pragma unroll
    for (int i = tid; i < 64 * 64; i += 256) {
        tl[i >> 6][i & 63] = src[(size_t)(i >> 6) * HS_ + (i & 63)];
    }
    __syncthreads();
    #pragma unroll
    for (int i = tid; i < 64 * 64; i += 256) {
        const int d = i >> 6, tt = i & 63;
        float x = tl[tt][d];
        __nv_bfloat16 h = __float2bfloat16_rn(x);
        __nv_bfloat16 l = __float2bfloat16_rn(x - __bfloat162float(h));
        const size_t o = (size_t)bh * HS_ * T_ + (size_t)d * T_ + t0 + tt;
        vth[o] = h;
        vtl[o] = l;
    }
}

// =========== HMMA strict-causal flash attention (q == k, bf16 split) ==========
// CTA: 128 queries, 8 warps x 16 rows; key tiles of 64. Writes y as bf16 hi/lo.
#define AQ 128
#define AK 64
#define APAD 72   // bf16 per smem row (144B, 16B-multiple)

__global__ void __launch_bounds__(256) attn_mma_k(
    const __nv_bfloat16* __restrict__ kh, const __nv_bfloat16* __restrict__ kl,
    const __nv_bfloat16* __restrict__ vth, const __nv_bfloat16* __restrict__ vtl,
    __nv_bfloat16* __restrict__ Yh, __nv_bfloat16* __restrict__ Yl)
{
    __shared__ __align__(16) __nv_bfloat16 sKh[AK][APAD];
    __shared__ __align__(16) __nv_bfloat16 sKl[AK][APAD];
    __shared__ __align__(16) __nv_bfloat16 sVh[HS_][APAD];
    __shared__ __align__(16) __nv_bfloat16 sVl[HS_][APAD];

    const int b = blockIdx.z;
    const int h = blockIdx.y;
    const int qb = gridDim.x - 1 - blockIdx.x;   // heavy blocks first
    const int p0 = qb * AQ;
    const int tid = threadIdx.x;
    const int wid = tid >> 5;
    const int lane = tid & 31;
    const int g = lane >> 2, t = lane & 3;
    const int wm = wid * 16;

    const __nv_bfloat16* Kh = kh + (((size_t)b * NH_ + h) * T_) * HS_;
    const __nv_bfloat16* Kl = kl + (((size_t)b * NH_ + h) * T_) * HS_;
    const __nv_bfloat16* Vh = vth + (((size_t)b * NH_ + h) * HS_) * T_;   // [d][t]
    const __nv_bfloat16* Vl = vtl + (((size_t)b * NH_ + h) * HS_) * T_;

    // ---- stage Q fragments (rows p0..p0+127 of K) ----
    uint32_t Qh[4][4], Ql[4][4];
    #pragma unroll
    for (int half = 0; half < 2; half++) {
        #pragma unroll
        for (int i = 0; i < 2; i++) {
            const int v = tid + i * 256;
            const int row = v >> 3, seg = v & 7;
            *(uint4*)&sKh[row][seg * 8] =
                *(const uint4*)(Kh + (size_t)(p0 + half * 64 + row) * HS_ + seg * 8);
            *(uint4*)&sKl[row][seg * 8] =
                *(const uint4*)(Kl + (size_t)(p0 + half * 64 + row) * HS_ + seg * 8);
        }
        __syncthreads();
        if ((wm >> 6) == half) {
            const int lr = wm & 63;
            #pragma unroll
            for (int ks = 0; ks < 4; ks++) {
                uint32_t a0 = smem_u32(&sKh[lr + (lane & 15)][ks*16 + ((lane>>4)&1)*8]);
                ldm_x4(Qh[ks][0], Qh[ks][1], Qh[ks][2], Qh[ks][3], a0);
                uint32_t a1 = smem_u32(&sKl[lr + (lane & 15)][ks*16 + ((lane>>4)&1)*8]);
                ldm_x4(Ql[ks][0], Ql[ks][1], Ql[ks][2], Ql[ks][3], a1);
            }
        }
        __syncthreads();
    }

    float m0 = -1e30f, m1 = -1e30f, l0 = 0.f, l1 = 0.f;
    float O[8][4];
    #pragma unroll
    for (int nj = 0; nj < 8; nj++)
        #pragma unroll
        for (int e = 0; e < 4; e++) O[nj][e] = 0.f;

    const int r0 = p0 + wm + g;
    const int r1 = r0 + 8;
    const int ntiles = (p0 + AQ) / AK;

    #pragma unroll 1
    for (int kt = 0; kt < ntiles; kt++) {
        const int j0 = kt * AK;
        // load K tile (rows = keys) and V^T tile (rows = dims, cols = keys)
        #pragma unroll
        for (int i = 0; i < 2; i++) {
            const int v = tid + i * 256;
            const int row = v >> 3, seg = v & 7;
            *(uint4*)&sKh[row][seg * 8] = *(const uint4*)(Kh + (size_t)(j0 + row) * HS_ + seg * 8);
            *(uint4*)&sKl[row][seg * 8] = *(const uint4*)(Kl + (size_t)(j0 + row) * HS_ + seg * 8);
            *(uint4*)&sVh[row][seg * 8] = *(const uint4*)(Vh + (size_t)row * T_ + j0 + seg * 8);
            *(uint4*)&sVl[row][seg * 8] = *(const uint4*)(Vl + (size_t)row * T_ + j0 + seg * 8);
        }
        __syncthreads();

        const bool active = (j0 < p0 + wm + 16);
        if (active) {
            float S[8][4];
            #pragma unroll
            for (int nj = 0; nj < 8; nj++)
                #pragma unroll
                for (int e = 0; e < 4; e++) S[nj][e] = 0.f;

            #pragma unroll
            for (int ks = 0; ks < 4; ks++) {
                const int koff = ks * 16;
                uint32_t bh2[8][2], bl2[8][2];
                #pragma unroll
                for (int nj = 0; nj < 8; nj++) {
                    ldm_x2(bh2[nj][0], bh2[nj][1],
                           smem_u32(&sKh[nj*8 + (lane&7)][koff + ((lane>>3)&1)*8]));
                    ldm_x2(bl2[nj][0], bl2[nj][1],
                           smem_u32(&sKl[nj*8 + (lane&7)][koff + ((lane>>3)&1)*8]));
                }
                #pragma unroll
                for (int nj = 0; nj < 8; nj++) {
                    mma_bf16(S[nj], Qh[ks], bh2[nj]);
                    mma_bf16(S[nj], Qh[ks], bl2[nj]);
                    mma_bf16(S[nj], Ql[ks], bh2[nj]);
                }
            }

            // causal mask (strict: key j valid iff j < p)
            if (j0 + AK > p0 + wm) {
                #pragma unroll
                for (int nj = 0; nj < 8; nj++) {
                    const int jb = j0 + nj*8 + 2*t;
                    if (jb     >= r0) S[nj][0] = -1e30f;
                    if (jb + 1 >= r0) S[nj][1] = -1e30f;
                    if (jb     >= r1) S[nj][2] = -1e30f;
                    if (jb + 1 >= r1) S[nj][3] = -1e30f;
                }
            }

            // row max
            float tm0 = -1e30f, tm1 = -1e30f;
            #pragma unroll
            for (int nj = 0; nj < 8; nj++) {
                tm0 = fmaxf(tm0, fmaxf(S[nj][0], S[nj][1]));
                tm1 = fmaxf(tm1, fmaxf(S[nj][2], S[nj][3]));
            }
            tm0 = fmaxf(tm0, __shfl_xor_sync(0xffffffffu, tm0, 1));
            tm0 = fmaxf(tm0, __shfl_xor_sync(0xffffffffu, tm0, 2));
            tm1 = fmaxf(tm1, __shfl_xor_sync(0xffffffffu, tm1, 1));
            tm1 = fmaxf(tm1, __shfl_xor_sync(0xffffffffu, tm1, 2));

            const float m0n = fmaxf(m0, tm0), m1n = fmaxf(m1, tm1);
            const float c0 = __expf(m0 - m0n), c1 = __expf(m1 - m1n);
            l0 *= c0; l1 *= c1;
            #pragma unroll
            for (int nj = 0; nj < 8; nj++) {
                O[nj][0] *= c0; O[nj][1] *= c0;
                O[nj][2] *= c1; O[nj][3] *= c1;
            }
            m0 = m0n; m1 = m1n;

            // exp, split P into bf16 hi/lo A-fragments, partial row sums
            uint32_t PhA[8][2], PlA[8][2];
            float s0 = 0.f, s1 = 0.f;
            #pragma unroll
            for (int nj = 0; nj < 8; nj++) {
                float e0 = __expf(S[nj][0] - m0n), e1 = __expf(S[nj][1] - m0n);
                float e2 = __expf(S[nj][2] - m1n), e3 = __expf(S[nj][3] - m1n);
                s0 += e0 + e1; s1 += e2 + e3;
                __nv_bfloat162 h01(__float2bfloat16_rn(e0), __float2bfloat16_rn(e1));
                __nv_bfloat162 h23(__float2bfloat16_rn(e2), __float2bfloat16_rn(e3));
                PhA[nj][0] = *(uint32_t*)&h01;
                PhA[nj][1] = *(uint32_t*)&h23;
                __nv_bfloat162 q01(__float2bfloat16_rn(e0 - __bfloat162float(h01.x)),
                                   __float2bfloat16_rn(e1 - __bfloat162float(h01.y)));
                __nv_bfloat162 q23(__float2bfloat16_rn(e2 - __bfloat162float(h23.x)),
                                   __float2bfloat16_rn(e3 - __bfloat162float(h23.y)));
                PlA[nj][0] = *(uint32_t*)&q01;
                PlA[nj][1] = *(uint32_t*)&q23;
            }
            s0 += __shfl_xor_sync(0xffffffffu, s0, 1);
            s0 += __shfl_xor_sync(0xffffffffu, s0, 2);
            s1 += __shfl_xor_sync(0xffffffffu, s1, 1);
            s1 += __shfl_xor_sync(0xffffffffu, s1, 2);
            l0 += s0; l1 += s1;

            // P @ V : 3 passes
            #pragma unroll
            for (int ks = 0; ks < 4; ks++) {
                const int koff = ks * 16;
                uint32_t ah[4] = {PhA[2*ks][0], PhA[2*ks][1], PhA[2*ks+1][0], PhA[2*ks+1][1]};
                uint32_t al[4] = {PlA[2*ks][0], PlA[2*ks][1], PlA[2*ks+1][0], PlA[2*ks+1][1]};
                #pragma unroll
                for (int nj = 0; nj < 8; nj++) {
                    uint32_t bv[2], bw[2];
                    ldm_x2(bv[0], bv[1],
                           smem_u32(&sVh[nj*8 + (lane&7)][koff + ((lane>>3)&1)*8]));
                    ldm_x2(bw[0], bw[1],
                           smem_u32(&sVl[nj*8 + (lane&7)][koff + ((lane>>3)&1)*8]));
                    mma_bf16(O[nj], ah, bv);
                    mma_bf16(O[nj], ah, bw);
                    mma_bf16(O[nj], al, bv);
                }
            }
        }
        __syncthreads();
    }

    // epilogue: y /= l; write bf16 hi/lo directly to proj-GEMM input buffers
    const float il0 = (r0 == 0) ? 0.f : 1.f / l0;
    const float il1 = 1.f / l1;
    __nv_bfloat16* y0h = Yh + ((size_t)b * T_ + r0) * C_ + h * HS_;
    __nv_bfloat16* y0l = Yl + ((size_t)b * T_ + r0) * C_ + h * HS_;
    __nv_bfloat16* y1h = Yh + ((size_t)b * T_ + r1) * C_ + h * HS_;
    __nv_bfloat16* y1l = Yl + ((size_t)b * T_ + r1) * C_ + h * HS_;
    #pragma unroll
    for (int nj = 0; nj < 8; nj++) {
        const int col = nj*8 + 2*t;
        float o0 = O[nj][0] * il0, o1 = O[nj][1] * il0;
        float o2 = O[nj][2] * il1, o3 = O[nj][3] * il1;
        __nv_bfloat162 h01(__float2bfloat16_rn(o0), __float2bfloat16_rn(o1));
        __nv_bfloat162 l01(__float2bfloat16_rn(o0 - __bfloat162float(h01.x)),
                           __float2bfloat16_rn(o1 - __bfloat162float(h01.y)));
        __nv_bfloat162 h23(__float2bfloat16_rn(o2), __float2bfloat16_rn(o3));
        __nv_bfloat162 l23(__float2bfloat16_rn(o2 - __bfloat162float(h23.x)),
                           __float2bfloat16_rn(o3 - __bfloat162float(h23.y)));
        *(__nv_bfloat162*)(y0h + col) = h01;
        *(__nv_bfloat162*)(y0l + col) = l01;
        *(__nv_bfloat162*)(y1h + col) = h23;
        *(__nv_bfloat162*)(y1l + col) = l23;
    }
}

// ------------------------------- launcher --------------------------------------
extern "C" void kernel_launch(void* const* d_in, const int* in_sizes, int n_in,
                              void* d_out, int out_size)
{
    const float* x           = (const float*)d_in[0];
    const float* W_la        = (const float*)d_in[1];
    const float* la_coef     = (const float*)d_in[2];
    const float* kernel_beta = (const float*)d_in[3];
    const float* value_beta  = (const float*)d_in[4];
    const float* W_v         = (const float*)d_in[5];
    const float* v_coef      = (const float*)d_in[6];
    const float* W_proj      = (const float*)d_in[7];
    float* out = (float*)d_out;

    float *xl, *xv, *kraw, *v;
    __nv_bfloat16 *Ah, *Al, *Wla_h, *Wla_l, *Wv_h, *Wv_l, *Wp_h, *Wp_l;
    __nv_bfloat16 *kh, *kl, *vth, *vtl;
    cudaGetSymbolAddress((void**)&xl,   g_xl);
    cudaGetSymbolAddress((void**)&xv,   g_xv);
    cudaGetSymbolAddress((void**)&kraw, g_kraw);
    cudaGetSymbolAddress((void**)&v,    g_v);
    cudaGetSymbolAddress((void**)&Ah,   g_Ah);
    cudaGetSymbolAddress((void**)&Al,   g_Al);
    cudaGetSymbolAddress((void**)&Wla_h, g_Wla_h);
    cudaGetSymbolAddress((void**)&Wla_l, g_Wla_l);
    cudaGetSymbolAddress((void**)&Wv_h,  g_Wv_h);
    cudaGetSymbolAddress((void**)&Wv_l,  g_Wv_l);
    cudaGetSymbolAddress((void**)&Wp_h,  g_Wp_h);
    cudaGetSymbolAddress((void**)&Wp_l,  g_Wp_l);
    cudaGetSymbolAddress((void**)&kh,   g_kh);
    cudaGetSymbolAddress((void**)&kl,   g_kl);
    cudaGetSymbolAddress((void**)&vth,  g_vth);
    cudaGetSymbolAddress((void**)&vtl,  g_vtl);

    const dim3 ggrid(C_ / GBN, M_ / GBM);
    const dim3 tgrid(32, 32), tblk(32, 8);
    const int n4 = (M_ * C_) / 4;

    split_bf16_k<<<(n4 + 255) / 256, 256>>>(x, Ah, Al, n4);
    tsplit_bf16_k<<<tgrid, tblk>>>(W_la,   Wla_h, Wla_l);
    tsplit_bf16_k<<<tgrid, tblk>>>(W_v,    Wv_h,  Wv_l);
    tsplit_bf16_k<<<tgrid, tblk>>>(W_proj, Wp_h,  Wp_l);

    gemm_tc_k<<<ggrid, 256>>>(Ah, Al, Wla_h, Wla_l, xl);
    gemm_tc_k<<<ggrid, 256>>>(Ah, Al, Wv_h,  Wv_l,  xv);

    ema_scan_k<<<(B_*C_)/256, 256>>>(xl, la_coef, kraw);

    knorm_bf16_k<<<(B_*NH_*T_)/8, 256>>>(kraw, kernel_beta, kh, kl);
    vmake_k<<<(B_*NH_*T_)/8, 256>>>(xv, v_coef, value_beta, v);
    vtsplit_k<<<dim3(T_/64, B_*NH_), 256>>>(v, vth, vtl);

    attn_mma_k<<<dim3(T_/AQ, NH_, B_), 256>>>(kh, kl, vth, vtl, Ah, Al);

    gemm_tc_k<<<ggrid, 256>>>(Ah, Al, Wp_h, Wp_l, out);
}